// round 13
// baseline (speedup 1.0000x reference)
#include <cuda_runtime.h>
#include <cuda_fp16.h>
#include <cstdint>

// ============================ problem dims ============================
#define M_TOTAL 8192   // 4 * 2048 tokens
#define K_DIM   2048
#define H_DIM   8192

// ============================ scratch (device globals; no allocs) ============================
__device__ __align__(128) __half g_xh [(size_t)M_TOTAL * K_DIM];   // x  -> fp16
__device__ __align__(128) __half g_wgh[(size_t)H_DIM   * K_DIM];   // w_gate -> fp16
__device__ __align__(128) __half g_wuh[(size_t)H_DIM   * K_DIM];   // w_up   -> fp16
__device__ __align__(128) __half g_wdh[(size_t)K_DIM   * H_DIM];   // w_down -> fp16
__device__ __align__(128) __half g_hid[(size_t)M_TOTAL * H_DIM];   // silu(g)*u in fp16
__device__ __align__(128) float  g_part[2][(size_t)M_TOTAL * K_DIM]; // split-K partials
__device__ unsigned g_tilecnt[16 * 64];                              // per-tile arrival counter

// ============================ helpers (plain sm_80+ PTX only) ============================
__device__ __forceinline__ uint32_t smem_u32(const void* p) {
    uint32_t a;
    asm("{ .reg .u64 t; cvta.to.shared.u64 t, %1; cvt.u32.u64 %0, t; }" : "=r"(a) : "l"(p));
    return a;
}
#define CP_ASYNC16(saddr, gptr) \
    asm volatile("cp.async.cg.shared.global [%0], [%1], 16;" :: "r"(saddr), "l"(gptr))
#define CP_COMMIT() asm volatile("cp.async.commit_group;" ::: "memory")
#define CP_WAIT(n)  asm volatile("cp.async.wait_group %0;" :: "n"(n) : "memory")

#define LDMATRIX_X4(R0, R1, R2, R3, addr) \
    asm volatile("ldmatrix.sync.aligned.m8n8.x4.shared.b16 {%0,%1,%2,%3}, [%4];" \
        : "=r"(R0), "=r"(R1), "=r"(R2), "=r"(R3) : "r"(addr))

__device__ __forceinline__ void mma_f16(float* c, const uint32_t* a, const uint32_t* b) {
    asm volatile(
        "mma.sync.aligned.m16n8k16.row.col.f32.f16.f16.f32 "
        "{%0,%1,%2,%3}, {%4,%5,%6,%7}, {%8,%9}, {%0,%1,%2,%3};"
        : "+f"(c[0]), "+f"(c[1]), "+f"(c[2]), "+f"(c[3])
        : "r"(a[0]), "r"(a[1]), "r"(a[2]), "r"(a[3]), "r"(b[0]), "r"(b[1]));
}

// ============================ tiling ============================
// Smem row = 32 halves (64B data) at 80B stride; 80 = 5*16 -> ldmatrix's 8 rows per
// phase land on 8 distinct 16B bank groups (conflict-free LDSM).
static constexpr int ROW_STRIDE_B = 80;
static constexpr int BK = 32;                          // k-halves per stage
static constexpr int STAGES = 5;                       // 5-deep cp.async pipeline
static constexpr int STAGE_ROWS  = 256;
static constexpr int STAGE_BYTES = STAGE_ROWS * ROW_STRIDE_B;        // 20480
static constexpr int SMEM_BYTES  = STAGES * STAGE_BYTES;             // 102400 -> 2 CTA/SM

// ============================ kernel 1: fused gate/up GEMM + SwiGLU ============================
// grid: (H/64, M/128), 128 threads. CTA: gate[128x64] + up[128x64] sharing the X tile.
// 4 warps as 2x2; warp 64x32 gate AND 64x32 up. LDSM.x4/MMA = 0.25 at 2 CTA/SM.
__global__ void __launch_bounds__(128, 2) gemm_gateup(
    const __half* __restrict__ X, const __half* __restrict__ Wg,
    const __half* __restrict__ Wu, __half* __restrict__ Hid) {
    extern __shared__ char smem[];
    const uint32_t sb = smem_u32(smem);

    const int tid = threadIdx.x;
    const int warp = tid >> 5, lane = tid & 31;
    const int warpM = warp >> 1, warpN = warp & 1;
    const int m0 = blockIdx.y * 128, n0 = blockIdx.x * 64;

    const int rr = tid >> 2;          // 0..31
    const int ch = tid & 3;           // 16B chunk in row

    const int KT = K_DIM / BK;        // 64

    auto load_stage = [&](int s, int kk) {
        const size_t kb = (size_t)kk * BK + ch * 8;      // in halves
        const uint32_t sd = sb + (uint32_t)(s * STAGE_BYTES + rr * ROW_STRIDE_B + ch * 16);
        CP_ASYNC16(sd,                       X  + (size_t)(m0 + rr)       * K_DIM + kb);
        CP_ASYNC16(sd +  32 * ROW_STRIDE_B,  X  + (size_t)(m0 + 32 + rr)  * K_DIM + kb);
        CP_ASYNC16(sd +  64 * ROW_STRIDE_B,  X  + (size_t)(m0 + 64 + rr)  * K_DIM + kb);
        CP_ASYNC16(sd +  96 * ROW_STRIDE_B,  X  + (size_t)(m0 + 96 + rr)  * K_DIM + kb);
        CP_ASYNC16(sd + 128 * ROW_STRIDE_B,  Wg + (size_t)(n0 + rr)       * K_DIM + kb);
        CP_ASYNC16(sd + 160 * ROW_STRIDE_B,  Wg + (size_t)(n0 + 32 + rr)  * K_DIM + kb);
        CP_ASYNC16(sd + 192 * ROW_STRIDE_B,  Wu + (size_t)(n0 + rr)       * K_DIM + kb);
        CP_ASYNC16(sd + 224 * ROW_STRIDE_B,  Wu + (size_t)(n0 + 32 + rr)  * K_DIM + kb);
        CP_COMMIT();
    };

    float accg[4][4][4], accu[4][4][4];
    #pragma unroll
    for (int mt = 0; mt < 4; mt++)
        #pragma unroll
        for (int nt = 0; nt < 4; nt++)
            #pragma unroll
            for (int j = 0; j < 4; j++) { accg[mt][nt][j] = 0.f; accu[mt][nt][j] = 0.f; }

    for (int s = 0; s < STAGES - 1; s++) load_stage(s, s);

    const uint32_t a_lo = (uint32_t)((lane & 15) * ROW_STRIDE_B + (lane >> 4) * 16);
    const uint32_t b_lo = (uint32_t)(((lane & 7) + ((lane >> 4) << 3)) * ROW_STRIDE_B
                                     + (((lane >> 3) & 1) << 4));

    int rd_stage = 0, wr_stage = STAGES - 1;
    for (int i = 0; i < KT; i++) {
        CP_WAIT(3);
        __syncthreads();
        const int nk = i + STAGES - 1;
        if (nk < KT) load_stage(wr_stage, nk);
        else         CP_COMMIT();            // keep group count in lockstep

        const uint32_t st = sb + (uint32_t)(rd_stage * STAGE_BYTES);

        uint32_t a[2][4][4], bg[2][8], bu[2][8];
        #pragma unroll
        for (int ks = 0; ks < 2; ks++) {          // all LDSM first
            const uint32_t kB = (uint32_t)(ks * 32);
            #pragma unroll
            for (int mt = 0; mt < 4; mt++) {
                const uint32_t addr = st + (uint32_t)((warpM * 64 + mt * 16) * ROW_STRIDE_B)
                                        + a_lo + kB;
                LDMATRIX_X4(a[ks][mt][0], a[ks][mt][1], a[ks][mt][2], a[ks][mt][3], addr);
            }
            const uint32_t ag = st + (uint32_t)((128 + warpN * 32) * ROW_STRIDE_B) + b_lo + kB;
            LDMATRIX_X4(bg[ks][0], bg[ks][1], bg[ks][2], bg[ks][3], ag);
            LDMATRIX_X4(bg[ks][4], bg[ks][5], bg[ks][6], bg[ks][7], ag + 16 * ROW_STRIDE_B);
            const uint32_t au = ag + 64 * ROW_STRIDE_B;
            LDMATRIX_X4(bu[ks][0], bu[ks][1], bu[ks][2], bu[ks][3], au);
            LDMATRIX_X4(bu[ks][4], bu[ks][5], bu[ks][6], bu[ks][7], au + 16 * ROW_STRIDE_B);
        }
        #pragma unroll
        for (int ks = 0; ks < 2; ks++) {          // then all MMA
            #pragma unroll
            for (int mt = 0; mt < 4; mt++) {
                #pragma unroll
                for (int nt = 0; nt < 4; nt++) {
                    mma_f16(accg[mt][nt], a[ks][mt], bg[ks] + 2 * nt);
                    mma_f16(accu[mt][nt], a[ks][mt], bu[ks] + 2 * nt);
                }
            }
        }
        if (++rd_stage == STAGES) rd_stage = 0;
        if (++wr_stage == STAGES) wr_stage = 0;
    }

    // epilogue: hid = silu(g) * u, direct fp16 pair stores (hidden under co-CTA mainloops)
    const int g4 = lane >> 2, t4 = lane & 3;
    #pragma unroll
    for (int mt = 0; mt < 4; mt++) {
        const int row = m0 + warpM * 64 + mt * 16 + g4;
        #pragma unroll
        for (int nt = 0; nt < 4; nt++) {
            const int col = n0 + warpN * 32 + nt * 8 + 2 * t4;
            #pragma unroll
            for (int h = 0; h < 2; h++) {
                const float gx = accg[mt][nt][2 * h],     ux = accu[mt][nt][2 * h];
                const float gy = accg[mt][nt][2 * h + 1], uy = accu[mt][nt][2 * h + 1];
                const float vx = gx * ux / (1.0f + __expf(-gx));
                const float vy = gy * uy / (1.0f + __expf(-gy));
                *reinterpret_cast<__half2*>(Hid + (size_t)(row + 8 * h) * H_DIM + col) =
                    __floats2half2_rn(vx, vy);
            }
        }
    }
}

// ============================ kernel 2: down GEMM, split-K=2, fused reduction ============
// grid: (16, 64, 2) = 2048 CTAs -> 6.92 waves. Each K half writes its partial buffer
// (plain STG, hidden); the SECOND CTA to finish a tile sums part0+part1 -> out
// (fixed operand order -> bitwise deterministic). The summation runs concurrently
// with other CTAs' mainloops instead of as a serial pass.
__global__ void __launch_bounds__(128, 2) gemm_down(
    const __half* __restrict__ A, const __half* __restrict__ B,
    float* __restrict__ Part, float* __restrict__ Out) {
    extern __shared__ char smem[];
    const uint32_t sb = smem_u32(smem);

    const int tid = threadIdx.x;
    const int warp = tid >> 5, lane = tid & 31;
    const int warpM = warp >> 1, warpN = warp & 1;
    const int m0 = blockIdx.y * 128, n0 = blockIdx.x * 128;
    const size_t k0 = (size_t)blockIdx.z * (H_DIM / 2);
    float* C = Part + (size_t)blockIdx.z * ((size_t)M_TOTAL * K_DIM);

    const int rr = tid >> 2;
    const int ch = tid & 3;

    const int KT = (H_DIM / 2) / BK;   // 128 per K half

    auto load_stage = [&](int s, int kk) {
        const size_t kb = k0 + (size_t)kk * BK + ch * 8;
        const uint32_t sd = sb + (uint32_t)(s * STAGE_BYTES + rr * ROW_STRIDE_B + ch * 16);
        CP_ASYNC16(sd,                       A + (size_t)(m0 + rr)       * H_DIM + kb);
        CP_ASYNC16(sd +  32 * ROW_STRIDE_B,  A + (size_t)(m0 + 32 + rr)  * H_DIM + kb);
        CP_ASYNC16(sd +  64 * ROW_STRIDE_B,  A + (size_t)(m0 + 64 + rr)  * H_DIM + kb);
        CP_ASYNC16(sd +  96 * ROW_STRIDE_B,  A + (size_t)(m0 + 96 + rr)  * H_DIM + kb);
        CP_ASYNC16(sd + 128 * ROW_STRIDE_B,  B + (size_t)(n0 + rr)       * H_DIM + kb);
        CP_ASYNC16(sd + 160 * ROW_STRIDE_B,  B + (size_t)(n0 + 32 + rr)  * H_DIM + kb);
        CP_ASYNC16(sd + 192 * ROW_STRIDE_B,  B + (size_t)(n0 + 64 + rr)  * H_DIM + kb);
        CP_ASYNC16(sd + 224 * ROW_STRIDE_B,  B + (size_t)(n0 + 96 + rr)  * H_DIM + kb);
        CP_COMMIT();
    };

    float acc[4][8][4];
    #pragma unroll
    for (int mt = 0; mt < 4; mt++)
        #pragma unroll
        for (int nt = 0; nt < 8; nt++)
            #pragma unroll
            for (int j = 0; j < 4; j++) acc[mt][nt][j] = 0.f;

    for (int s = 0; s < STAGES - 1; s++) load_stage(s, s);

    const uint32_t a_lo = (uint32_t)((lane & 15) * ROW_STRIDE_B + (lane >> 4) * 16);
    const uint32_t b_lo = (uint32_t)(((lane & 7) + ((lane >> 4) << 3)) * ROW_STRIDE_B
                                     + (((lane >> 3) & 1) << 4));

    int rd_stage = 0, wr_stage = STAGES - 1;
    for (int i = 0; i < KT; i++) {
        CP_WAIT(3);
        __syncthreads();
        const int nk = i + STAGES - 1;
        if (nk < KT) load_stage(wr_stage, nk);
        else         CP_COMMIT();

        const uint32_t st = sb + (uint32_t)(rd_stage * STAGE_BYTES);

        uint32_t a[2][4][4], b[2][16];
        #pragma unroll
        for (int ks = 0; ks < 2; ks++) {          // all LDSM first
            const uint32_t kB = (uint32_t)(ks * 32);
            #pragma unroll
            for (int mt = 0; mt < 4; mt++) {
                const uint32_t addr = st + (uint32_t)((warpM * 64 + mt * 16) * ROW_STRIDE_B)
                                        + a_lo + kB;
                LDMATRIX_X4(a[ks][mt][0], a[ks][mt][1], a[ks][mt][2], a[ks][mt][3], addr);
            }
            const uint32_t ab = st + (uint32_t)((128 + warpN * 64) * ROW_STRIDE_B) + b_lo + kB;
            LDMATRIX_X4(b[ks][0],  b[ks][1],  b[ks][2],  b[ks][3],  ab);
            LDMATRIX_X4(b[ks][4],  b[ks][5],  b[ks][6],  b[ks][7],  ab + 16 * ROW_STRIDE_B);
            LDMATRIX_X4(b[ks][8],  b[ks][9],  b[ks][10], b[ks][11], ab + 32 * ROW_STRIDE_B);
            LDMATRIX_X4(b[ks][12], b[ks][13], b[ks][14], b[ks][15], ab + 48 * ROW_STRIDE_B);
        }
        #pragma unroll
        for (int ks = 0; ks < 2; ks++)            // then all MMA
            #pragma unroll
            for (int mt = 0; mt < 4; mt++)
                #pragma unroll
                for (int nt = 0; nt < 8; nt++)
                    mma_f16(acc[mt][nt], a[ks][mt], b[ks] + 2 * nt);

        if (++rd_stage == STAGES) rd_stage = 0;
        if (++wr_stage == STAGES) wr_stage = 0;
    }

    // ---- write partial tile ----
    const int g4 = lane >> 2, t4 = lane & 3;
    #pragma unroll
    for (int mt = 0; mt < 4; mt++) {
        const int row = m0 + warpM * 64 + mt * 16 + g4;
        #pragma unroll
        for (int nt = 0; nt < 8; nt++) {
            const int col = n0 + warpN * 64 + nt * 8 + 2 * t4;
            *reinterpret_cast<float2*>(C + (size_t)row * K_DIM + col) =
                make_float2(acc[mt][nt][0], acc[mt][nt][1]);
            *reinterpret_cast<float2*>(C + (size_t)(row + 8) * K_DIM + col) =
                make_float2(acc[mt][nt][2], acc[mt][nt][3]);
        }
    }

    // ---- last-CTA-wins fused reduction ----
    __threadfence();                                  // release partial writes
    __syncthreads();                                  // all threads' STGs issued
    __shared__ unsigned s_old;
    if (tid == 0)
        s_old = atomicAdd(&g_tilecnt[blockIdx.y * 16 + blockIdx.x], 1u);
    __syncthreads();
    if (s_old == 1) {                                 // second arriver sums the tile
        __threadfence();                              // acquire other CTA's writes
        const float4* p0 = reinterpret_cast<const float4*>(Part);
        const float4* p1 = reinterpret_cast<const float4*>(Part + (size_t)M_TOTAL * K_DIM);
        float4* po = reinterpret_cast<float4*>(Out);
        // tile = 128 rows x 32 float4; unit u: warp covers one row's 32 float4 (coalesced)
        #pragma unroll
        for (int it = 0; it < 32; it++) {
            const int u = it * 128 + tid;
            const int row = u >> 5, c4 = u & 31;
            const size_t idx = ((size_t)(m0 + row) * K_DIM + n0) / 4 + c4;
            const float4 va = p0[idx], vb = p1[idx];
            po[idx] = make_float4(va.x + vb.x, va.y + vb.y, va.z + vb.z, va.w + vb.w);
        }
    }
}

// ============================ conversion kernel ============================
__global__ void __launch_bounds__(256) f32_to_f16_kernel(const float4* __restrict__ src,
                                                         uint2* __restrict__ dst, int n4) {
    int i = blockIdx.x * blockDim.x + threadIdx.x;
    const int stride = gridDim.x * blockDim.x;
    for (; i < n4; i += stride) {
        const float4 v = __ldcs(src + i);   // single-use source: streaming load
        const __half2 h0 = __floats2half2_rn(v.x, v.y);
        const __half2 h1 = __floats2half2_rn(v.z, v.w);
        uint2 o;
        o.x = *reinterpret_cast<const uint32_t*>(&h0);
        o.y = *reinterpret_cast<const uint32_t*>(&h1);
        dst[i] = o;
    }
}

// ============================ host side ============================
extern "C" void kernel_launch(void* const* d_in, const int* in_sizes, int n_in,
                              void* d_out, int out_size) {
    const float* x  = (const float*)d_in[0];
    const float* wg = (const float*)d_in[1];
    const float* wu = (const float*)d_in[2];
    const float* wd = (const float*)d_in[3];
    float* out = (float*)d_out;

    void *p_xh, *p_wgh, *p_wuh, *p_wdh, *p_hid, *p_part, *p_cnt;
    cudaGetSymbolAddress(&p_xh,   g_xh);
    cudaGetSymbolAddress(&p_wgh,  g_wgh);
    cudaGetSymbolAddress(&p_wuh,  g_wuh);
    cudaGetSymbolAddress(&p_wdh,  g_wdh);
    cudaGetSymbolAddress(&p_hid,  g_hid);
    cudaGetSymbolAddress(&p_part, g_part);
    cudaGetSymbolAddress(&p_cnt,  g_tilecnt);

    cudaFuncSetAttribute(gemm_gateup, cudaFuncAttributeMaxDynamicSharedMemorySize, SMEM_BYTES);
    cudaFuncSetAttribute(gemm_down,   cudaFuncAttributeMaxDynamicSharedMemorySize, SMEM_BYTES);

    // 0) reset per-tile counters (graph-capturable async memset; 4KB)
    cudaMemsetAsync(p_cnt, 0, 16 * 64 * sizeof(unsigned));

    // 1) fp32 -> fp16 (4 separate launches — measured faster than fused)
    const int n4 = (M_TOTAL * K_DIM) / 4;   // all four arrays are equal-sized
    f32_to_f16_kernel<<<2048, 256>>>((const float4*)x,  (uint2*)p_xh,  n4);
    f32_to_f16_kernel<<<2048, 256>>>((const float4*)wg, (uint2*)p_wgh, n4);
    f32_to_f16_kernel<<<2048, 256>>>((const float4*)wu, (uint2*)p_wuh, n4);
    f32_to_f16_kernel<<<2048, 256>>>((const float4*)wd, (uint2*)p_wdh, n4);

    // 2) fused gate/up + SwiGLU -> fp16 hidden
    gemm_gateup<<<dim3(H_DIM / 64, M_TOTAL / 128), 128, SMEM_BYTES>>>(
        (const __half*)p_xh, (const __half*)p_wgh, (const __half*)p_wuh, (__half*)p_hid);

    // 3) down GEMM, split-K=2 with fused last-CTA reduction -> out
    gemm_down<<<dim3(K_DIM / 128, M_TOTAL / 128, 2), 128, SMEM_BYTES>>>(
        (const __half*)p_hid, (const __half*)p_wdh, (float*)p_part, out);
}

// round 14
// speedup vs baseline: 1.0318x; 1.0318x over previous
#include <cuda_runtime.h>
#include <cuda_fp16.h>
#include <cstdint>

// ============================ problem dims ============================
#define M_TOTAL 8192   // 4 * 2048 tokens
#define K_DIM   2048
#define H_DIM   8192

// ============================ scratch (device globals; no allocs) ============================
__device__ __align__(128) __half g_xh [(size_t)M_TOTAL * K_DIM];   // x  -> fp16
__device__ __align__(128) __half g_wgh[(size_t)H_DIM   * K_DIM];   // w_gate -> fp16
__device__ __align__(128) __half g_wuh[(size_t)H_DIM   * K_DIM];   // w_up   -> fp16
__device__ __align__(128) __half g_wdh[(size_t)K_DIM   * H_DIM];   // w_down -> fp16
__device__ __align__(128) __half g_hid[(size_t)M_TOTAL * H_DIM];   // silu(g)*u in fp16

// ============================ helpers (plain sm_80+ PTX only) ============================
__device__ __forceinline__ uint32_t smem_u32(const void* p) {
    uint32_t a;
    asm("{ .reg .u64 t; cvta.to.shared.u64 t, %1; cvt.u32.u64 %0, t; }" : "=r"(a) : "l"(p));
    return a;
}
#define CP_ASYNC16(saddr, gptr) \
    asm volatile("cp.async.cg.shared.global [%0], [%1], 16;" :: "r"(saddr), "l"(gptr))
#define CP_COMMIT() asm volatile("cp.async.commit_group;" ::: "memory")
#define CP_WAIT(n)  asm volatile("cp.async.wait_group %0;" :: "n"(n) : "memory")

#define LDMATRIX_X4(R0, R1, R2, R3, addr) \
    asm volatile("ldmatrix.sync.aligned.m8n8.x4.shared.b16 {%0,%1,%2,%3}, [%4];" \
        : "=r"(R0), "=r"(R1), "=r"(R2), "=r"(R3) : "r"(addr))

__device__ __forceinline__ void mma_f16(float* c, const uint32_t* a, const uint32_t* b) {
    asm volatile(
        "mma.sync.aligned.m16n8k16.row.col.f32.f16.f16.f32 "
        "{%0,%1,%2,%3}, {%4,%5,%6,%7}, {%8,%9}, {%0,%1,%2,%3};"
        : "+f"(c[0]), "+f"(c[1]), "+f"(c[2]), "+f"(c[3])
        : "r"(a[0]), "r"(a[1]), "r"(a[2]), "r"(a[3]), "r"(b[0]), "r"(b[1]));
}

__device__ __forceinline__ void red_add_f32(float* p, float v) {
    asm volatile("red.global.add.f32 [%0], %1;" :: "l"(p), "f"(v) : "memory");
}

// ============================ tiling ============================
// Smem row = 32 halves (64B data) at 80B stride; 80 = 5*16 -> ldmatrix's 8 rows per
// phase land on 8 distinct 16B bank groups (conflict-free LDSM).
static constexpr int ROW_STRIDE_B = 80;
static constexpr int BK = 32;                          // k-halves per stage
static constexpr int STAGES = 5;                       // 5-deep cp.async pipeline
static constexpr int STAGE_ROWS  = 256;
static constexpr int STAGE_BYTES = STAGE_ROWS * ROW_STRIDE_B;        // 20480
static constexpr int SMEM_BYTES  = STAGES * STAGE_BYTES;             // 102400 -> 2 CTA/SM

// ============================ kernel 1: fused gate/up GEMM + SwiGLU ============================
// grid: (H/64, M/128), 128 threads. CTA: gate[128x64] + up[128x64] sharing the X tile.
// 4 warps as 2x2; warp 64x32 gate AND 64x32 up. LDSM.x4/MMA = 0.25 at 2 CTA/SM.
__global__ void __launch_bounds__(128, 2) gemm_gateup(
    const __half* __restrict__ X, const __half* __restrict__ Wg,
    const __half* __restrict__ Wu, __half* __restrict__ Hid) {
    extern __shared__ char smem[];
    const uint32_t sb = smem_u32(smem);

    const int tid = threadIdx.x;
    const int warp = tid >> 5, lane = tid & 31;
    const int warpM = warp >> 1, warpN = warp & 1;
    const int m0 = blockIdx.y * 128, n0 = blockIdx.x * 64;

    const int rr = tid >> 2;          // 0..31
    const int ch = tid & 3;           // 16B chunk in row

    const int KT = K_DIM / BK;        // 64

    auto load_stage = [&](int s, int kk) {
        const size_t kb = (size_t)kk * BK + ch * 8;      // in halves
        const uint32_t sd = sb + (uint32_t)(s * STAGE_BYTES + rr * ROW_STRIDE_B + ch * 16);
        CP_ASYNC16(sd,                       X  + (size_t)(m0 + rr)       * K_DIM + kb);
        CP_ASYNC16(sd +  32 * ROW_STRIDE_B,  X  + (size_t)(m0 + 32 + rr)  * K_DIM + kb);
        CP_ASYNC16(sd +  64 * ROW_STRIDE_B,  X  + (size_t)(m0 + 64 + rr)  * K_DIM + kb);
        CP_ASYNC16(sd +  96 * ROW_STRIDE_B,  X  + (size_t)(m0 + 96 + rr)  * K_DIM + kb);
        CP_ASYNC16(sd + 128 * ROW_STRIDE_B,  Wg + (size_t)(n0 + rr)       * K_DIM + kb);
        CP_ASYNC16(sd + 160 * ROW_STRIDE_B,  Wg + (size_t)(n0 + 32 + rr)  * K_DIM + kb);
        CP_ASYNC16(sd + 192 * ROW_STRIDE_B,  Wu + (size_t)(n0 + rr)       * K_DIM + kb);
        CP_ASYNC16(sd + 224 * ROW_STRIDE_B,  Wu + (size_t)(n0 + 32 + rr)  * K_DIM + kb);
        CP_COMMIT();
    };

    float accg[4][4][4], accu[4][4][4];
    #pragma unroll
    for (int mt = 0; mt < 4; mt++)
        #pragma unroll
        for (int nt = 0; nt < 4; nt++)
            #pragma unroll
            for (int j = 0; j < 4; j++) { accg[mt][nt][j] = 0.f; accu[mt][nt][j] = 0.f; }

    for (int s = 0; s < STAGES - 1; s++) load_stage(s, s);

    const uint32_t a_lo = (uint32_t)((lane & 15) * ROW_STRIDE_B + (lane >> 4) * 16);
    const uint32_t b_lo = (uint32_t)(((lane & 7) + ((lane >> 4) << 3)) * ROW_STRIDE_B
                                     + (((lane >> 3) & 1) << 4));

    int rd_stage = 0, wr_stage = STAGES - 1;
    for (int i = 0; i < KT; i++) {
        CP_WAIT(3);
        __syncthreads();
        const int nk = i + STAGES - 1;
        if (nk < KT) load_stage(wr_stage, nk);
        else         CP_COMMIT();            // keep group count in lockstep

        const uint32_t st = sb + (uint32_t)(rd_stage * STAGE_BYTES);

        uint32_t a[2][4][4], bg[2][8], bu[2][8];
        #pragma unroll
        for (int ks = 0; ks < 2; ks++) {          // all LDSM first
            const uint32_t kB = (uint32_t)(ks * 32);
            #pragma unroll
            for (int mt = 0; mt < 4; mt++) {
                const uint32_t addr = st + (uint32_t)((warpM * 64 + mt * 16) * ROW_STRIDE_B)
                                        + a_lo + kB;
                LDMATRIX_X4(a[ks][mt][0], a[ks][mt][1], a[ks][mt][2], a[ks][mt][3], addr);
            }
            const uint32_t ag = st + (uint32_t)((128 + warpN * 32) * ROW_STRIDE_B) + b_lo + kB;
            LDMATRIX_X4(bg[ks][0], bg[ks][1], bg[ks][2], bg[ks][3], ag);
            LDMATRIX_X4(bg[ks][4], bg[ks][5], bg[ks][6], bg[ks][7], ag + 16 * ROW_STRIDE_B);
            const uint32_t au = ag + 64 * ROW_STRIDE_B;
            LDMATRIX_X4(bu[ks][0], bu[ks][1], bu[ks][2], bu[ks][3], au);
            LDMATRIX_X4(bu[ks][4], bu[ks][5], bu[ks][6], bu[ks][7], au + 16 * ROW_STRIDE_B);
        }
        #pragma unroll
        for (int ks = 0; ks < 2; ks++) {          // then all MMA
            #pragma unroll
            for (int mt = 0; mt < 4; mt++) {
                #pragma unroll
                for (int nt = 0; nt < 4; nt++) {
                    mma_f16(accg[mt][nt], a[ks][mt], bg[ks] + 2 * nt);
                    mma_f16(accu[mt][nt], a[ks][mt], bu[ks] + 2 * nt);
                }
            }
        }
        if (++rd_stage == STAGES) rd_stage = 0;
        if (++wr_stage == STAGES) wr_stage = 0;
    }

    // epilogue: hid = silu(g) * u, direct fp16 pair stores (hidden under co-CTA mainloops)
    const int g4 = lane >> 2, t4 = lane & 3;
    #pragma unroll
    for (int mt = 0; mt < 4; mt++) {
        const int row = m0 + warpM * 64 + mt * 16 + g4;
        #pragma unroll
        for (int nt = 0; nt < 4; nt++) {
            const int col = n0 + warpN * 32 + nt * 8 + 2 * t4;
            #pragma unroll
            for (int h = 0; h < 2; h++) {
                const float gx = accg[mt][nt][2 * h],     ux = accu[mt][nt][2 * h];
                const float gy = accg[mt][nt][2 * h + 1], uy = accu[mt][nt][2 * h + 1];
                const float vx = gx * ux / (1.0f + __expf(-gx));
                const float vy = gy * uy / (1.0f + __expf(-gy));
                *reinterpret_cast<__half2*>(Hid + (size_t)(row + 8 * h) * H_DIM + col) =
                    __floats2half2_rn(vx, vy);
            }
        }
    }
}

// ============================ kernel 2: down GEMM, split-K=2 ============================
// grid: (16, 64, 2) = 2048 CTAs -> 6.92 waves. red.global.add onto zeroed C
// (exactly 2 commutative adds onto 0 -> bitwise deterministic).
__global__ void __launch_bounds__(128, 2) gemm_down(
    const __half* __restrict__ A, const __half* __restrict__ B, float* __restrict__ C) {
    extern __shared__ char smem[];
    const uint32_t sb = smem_u32(smem);

    const int tid = threadIdx.x;
    const int warp = tid >> 5, lane = tid & 31;
    const int warpM = warp >> 1, warpN = warp & 1;
    const int m0 = blockIdx.y * 128, n0 = blockIdx.x * 128;
    const size_t k0 = (size_t)blockIdx.z * (H_DIM / 2);

    const int rr = tid >> 2;
    const int ch = tid & 3;

    const int KT = (H_DIM / 2) / BK;   // 128 per K half

    auto load_stage = [&](int s, int kk) {
        const size_t kb = k0 + (size_t)kk * BK + ch * 8;
        const uint32_t sd = sb + (uint32_t)(s * STAGE_BYTES + rr * ROW_STRIDE_B + ch * 16);
        CP_ASYNC16(sd,                       A + (size_t)(m0 + rr)       * H_DIM + kb);
        CP_ASYNC16(sd +  32 * ROW_STRIDE_B,  A + (size_t)(m0 + 32 + rr)  * H_DIM + kb);
        CP_ASYNC16(sd +  64 * ROW_STRIDE_B,  A + (size_t)(m0 + 64 + rr)  * H_DIM + kb);
        CP_ASYNC16(sd +  96 * ROW_STRIDE_B,  A + (size_t)(m0 + 96 + rr)  * H_DIM + kb);
        CP_ASYNC16(sd + 128 * ROW_STRIDE_B,  B + (size_t)(n0 + rr)       * H_DIM + kb);
        CP_ASYNC16(sd + 160 * ROW_STRIDE_B,  B + (size_t)(n0 + 32 + rr)  * H_DIM + kb);
        CP_ASYNC16(sd + 192 * ROW_STRIDE_B,  B + (size_t)(n0 + 64 + rr)  * H_DIM + kb);
        CP_ASYNC16(sd + 224 * ROW_STRIDE_B,  B + (size_t)(n0 + 96 + rr)  * H_DIM + kb);
        CP_COMMIT();
    };

    float acc[4][8][4];
    #pragma unroll
    for (int mt = 0; mt < 4; mt++)
        #pragma unroll
        for (int nt = 0; nt < 8; nt++)
            #pragma unroll
            for (int j = 0; j < 4; j++) acc[mt][nt][j] = 0.f;

    for (int s = 0; s < STAGES - 1; s++) load_stage(s, s);

    const uint32_t a_lo = (uint32_t)((lane & 15) * ROW_STRIDE_B + (lane >> 4) * 16);
    const uint32_t b_lo = (uint32_t)(((lane & 7) + ((lane >> 4) << 3)) * ROW_STRIDE_B
                                     + (((lane >> 3) & 1) << 4));

    int rd_stage = 0, wr_stage = STAGES - 1;
    for (int i = 0; i < KT; i++) {
        CP_WAIT(3);
        __syncthreads();
        const int nk = i + STAGES - 1;
        if (nk < KT) load_stage(wr_stage, nk);
        else         CP_COMMIT();

        const uint32_t st = sb + (uint32_t)(rd_stage * STAGE_BYTES);

        uint32_t a[2][4][4], b[2][16];
        #pragma unroll
        for (int ks = 0; ks < 2; ks++) {          // all LDSM first
            const uint32_t kB = (uint32_t)(ks * 32);
            #pragma unroll
            for (int mt = 0; mt < 4; mt++) {
                const uint32_t addr = st + (uint32_t)((warpM * 64 + mt * 16) * ROW_STRIDE_B)
                                        + a_lo + kB;
                LDMATRIX_X4(a[ks][mt][0], a[ks][mt][1], a[ks][mt][2], a[ks][mt][3], addr);
            }
            const uint32_t ab = st + (uint32_t)((128 + warpN * 64) * ROW_STRIDE_B) + b_lo + kB;
            LDMATRIX_X4(b[ks][0],  b[ks][1],  b[ks][2],  b[ks][3],  ab);
            LDMATRIX_X4(b[ks][4],  b[ks][5],  b[ks][6],  b[ks][7],  ab + 16 * ROW_STRIDE_B);
            LDMATRIX_X4(b[ks][8],  b[ks][9],  b[ks][10], b[ks][11], ab + 32 * ROW_STRIDE_B);
            LDMATRIX_X4(b[ks][12], b[ks][13], b[ks][14], b[ks][15], ab + 48 * ROW_STRIDE_B);
        }
        #pragma unroll
        for (int ks = 0; ks < 2; ks++)            // then all MMA
            #pragma unroll
            for (int mt = 0; mt < 4; mt++)
                #pragma unroll
                for (int nt = 0; nt < 8; nt++)
                    mma_f16(acc[mt][nt], a[ks][mt], b[ks] + 2 * nt);

        if (++rd_stage == STAGES) rd_stage = 0;
        if (++wr_stage == STAGES) wr_stage = 0;
    }

    const int g4 = lane >> 2, t4 = lane & 3;
    #pragma unroll
    for (int mt = 0; mt < 4; mt++) {
        const int row = m0 + warpM * 64 + mt * 16 + g4;
        #pragma unroll
        for (int nt = 0; nt < 8; nt++) {
            const int col = n0 + warpN * 64 + nt * 8 + 2 * t4;
            float* p0 = C + (size_t)row * K_DIM + col;
            float* p1 = C + (size_t)(row + 8) * K_DIM + col;
            red_add_f32(p0,     acc[mt][nt][0]);
            red_add_f32(p0 + 1, acc[mt][nt][1]);
            red_add_f32(p1,     acc[mt][nt][2]);
            red_add_f32(p1 + 1, acc[mt][nt][3]);
        }
    }
}

// ============================ elementwise kernels ============================
// Exact-trip MLP-8 convert: n4 = 2048 blocks * 256 threads * 8 contiguous-strided
// float4 per thread. All 8 loads issue back-to-back (front-batched -> MLP=8).
__global__ void __launch_bounds__(256) f32_to_f16_kernel(const float4* __restrict__ src,
                                                         uint2* __restrict__ dst) {
    const int base = blockIdx.x * 2048 + threadIdx.x;
    float4 v[8];
    #pragma unroll
    for (int j = 0; j < 8; j++) v[j] = src[base + j * 256];
    #pragma unroll
    for (int j = 0; j < 8; j++) {
        const __half2 h0 = __floats2half2_rn(v[j].x, v[j].y);
        const __half2 h1 = __floats2half2_rn(v[j].z, v[j].w);
        uint2 o;
        o.x = *reinterpret_cast<const uint32_t*>(&h0);
        o.y = *reinterpret_cast<const uint32_t*>(&h1);
        dst[base + j * 256] = o;
    }
}

// Exact-trip zero: 2048 blocks * 256 threads * 8 float4 = 16M floats = 64 MB
__global__ void __launch_bounds__(256) zero_kernel(float4* __restrict__ dst) {
    const int base = blockIdx.x * 2048 + threadIdx.x;
    const float4 z = make_float4(0.f, 0.f, 0.f, 0.f);
    #pragma unroll
    for (int j = 0; j < 8; j++) dst[base + j * 256] = z;
}

// ============================ host side ============================
extern "C" void kernel_launch(void* const* d_in, const int* in_sizes, int n_in,
                              void* d_out, int out_size) {
    const float* x  = (const float*)d_in[0];
    const float* wg = (const float*)d_in[1];
    const float* wu = (const float*)d_in[2];
    const float* wd = (const float*)d_in[3];
    float* out = (float*)d_out;

    void *p_xh, *p_wgh, *p_wuh, *p_wdh, *p_hid;
    cudaGetSymbolAddress(&p_xh,  g_xh);
    cudaGetSymbolAddress(&p_wgh, g_wgh);
    cudaGetSymbolAddress(&p_wuh, g_wuh);
    cudaGetSymbolAddress(&p_wdh, g_wdh);
    cudaGetSymbolAddress(&p_hid, g_hid);

    cudaFuncSetAttribute(gemm_gateup, cudaFuncAttributeMaxDynamicSharedMemorySize, SMEM_BYTES);
    cudaFuncSetAttribute(gemm_down,   cudaFuncAttributeMaxDynamicSharedMemorySize, SMEM_BYTES);

    // 0) zero the output (split-K accumulates into it); 16M floats / (2048*256*8) exact
    zero_kernel<<<2048, 256>>>((float4*)out);

    // 1) fp32 -> fp16 (4 separate launches; exact-trip, MLP=8)
    f32_to_f16_kernel<<<2048, 256>>>((const float4*)x,  (uint2*)p_xh);
    f32_to_f16_kernel<<<2048, 256>>>((const float4*)wg, (uint2*)p_wgh);
    f32_to_f16_kernel<<<2048, 256>>>((const float4*)wu, (uint2*)p_wuh);
    f32_to_f16_kernel<<<2048, 256>>>((const float4*)wd, (uint2*)p_wdh);

    // 2) fused gate/up + SwiGLU -> fp16 hidden
    gemm_gateup<<<dim3(H_DIM / 64, M_TOTAL / 128), 128, SMEM_BYTES>>>(
        (const __half*)p_xh, (const __half*)p_wgh, (const __half*)p_wuh, (__half*)p_hid);

    // 3) down GEMM, split-K=2 -> accumulate into out
    gemm_down<<<dim3(K_DIM / 128, M_TOTAL / 128, 2), 128, SMEM_BYTES>>>(
        (const __half*)p_hid, (const __half*)p_wdh, out);
}